// round 15
// baseline (speedup 1.0000x reference)
#include <cuda_runtime.h>
#include <cuda_fp16.h>
#include <cstdint>

#define N_NODES 4096
#define IN_F    512
#define NHEADS  4
#define OUT_F   64
#define C_TOT   256
#define ALPHA   0.2f
#define ESHIFT  2.0f

// ---------------- scratch ----------------
__device__ __half   g_hT  [C_TOT * N_NODES];      // [(h*64+f)][j]  fp16
__device__ __half   g_xh  [N_NODES * IN_F];       // x in fp16
__device__ __half   g_WTh [C_TOT * IN_F];         // W^T in fp16 [n][k]
__device__ __half2  g_esh [NHEADS * N_NODES];     // (exp(s-2), exp(a*s-2))  i-side
__device__ __half2  g_ee  [NHEADS * N_NODES];     // (exp(t-2), exp(a*t-2))  j-side
__device__ uint32_t g_adjbits[N_NODES * (N_NODES / 32)];

// ---------------- helpers ----------------
__device__ __forceinline__ uint32_t smem_u32(const void* p) {
    uint32_t a;
    asm("{ .reg .u64 t; cvta.to.shared.u64 t, %1; cvt.u32.u64 %0, t; }"
        : "=r"(a) : "l"(p));
    return a;
}
__device__ __forceinline__ uint32_t hmul2u(uint32_t a, uint32_t b) {
    uint32_t r; asm("mul.f16x2 %0, %1, %2;" : "=r"(r) : "r"(a), "r"(b)); return r;
}
__device__ __forceinline__ uint32_t hmax2u(uint32_t a, uint32_t b) {
    uint32_t r; asm("max.f16x2 %0, %1, %2;" : "=r"(r) : "r"(a), "r"(b)); return r;
}
__device__ __forceinline__ void mma_f16_16n8k16(float* d, const uint32_t* a,
                                                uint32_t b0, uint32_t b1) {
    asm volatile(
        "mma.sync.aligned.m16n8k16.row.col.f32.f16.f16.f32 "
        "{%0,%1,%2,%3}, {%4,%5,%6,%7}, {%8,%9}, {%0,%1,%2,%3};"
        : "+f"(d[0]), "+f"(d[1]), "+f"(d[2]), "+f"(d[3])
        : "r"(a[0]), "r"(a[1]), "r"(a[2]), "r"(a[3]), "r"(b0), "r"(b1));
}
__device__ __forceinline__ void ldmat_x4(uint32_t* r, uint32_t addr) {
    asm volatile("ldmatrix.sync.aligned.m8n8.x4.shared.b16 {%0,%1,%2,%3}, [%4];"
        : "=r"(r[0]), "=r"(r[1]), "=r"(r[2]), "=r"(r[3]) : "r"(addr));
}

// ---------------- kernel P: fused prep (pack_adj | conv_x | transpose_w) -----
// pack: each warp -> 8 words (256 ints), MLP=8 coalesced loads, 2 x STG.128
#define PREP_PACK   8192
#define PREP_CONV   2048
#define PREP_TRANS  128
#define PREP_BLOCKS (PREP_PACK + PREP_CONV + PREP_TRANS)

__global__ __launch_bounds__(256) void prep(const float* __restrict__ x,
                                            const int* __restrict__ adj,
                                            const float* __restrict__ W) {
    __shared__ float t[32][33];
    int b = blockIdx.x;
    if (b < PREP_PACK) {
        int gw = b * 8 + (threadIdx.x >> 5);          // global warp -> 8 words
        int lane = threadIdx.x & 31;
        const int* base = adj + gw * 256;
        int v[8];
        #pragma unroll
        for (int i = 0; i < 8; i++) v[i] = base[i * 32 + lane];
        uint32_t w[8];
        #pragma unroll
        for (int i = 0; i < 8; i++) w[i] = __ballot_sync(0xffffffffu, v[i] > 0);
        if (lane == 0) {
            *(uint4*)&g_adjbits[gw * 8]     = make_uint4(w[0], w[1], w[2], w[3]);
            *(uint4*)&g_adjbits[gw * 8 + 4] = make_uint4(w[4], w[5], w[6], w[7]);
        }
    } else if (b < PREP_PACK + PREP_CONV) {
        int idx = (b - PREP_PACK) * 256 + threadIdx.x;
        float4 v = ((const float4*)x)[idx];
        __half2 lo = __floats2half2_rn(v.x, v.y);
        __half2 hi = __floats2half2_rn(v.z, v.w);
        uint2 o = { *(uint32_t*)&lo, *(uint32_t*)&hi };
        ((uint2*)g_xh)[idx] = o;
    } else {
        int bb = b - PREP_PACK - PREP_CONV;            // 0..127
        int kx = (bb & 15) * 32, nx = (bb >> 4) * 32;
        int lx = threadIdx.x & 31, ly = threadIdx.x >> 5;
        #pragma unroll
        for (int q = 0; q < 4; q++)
            t[ly + q*8][lx] = W[(kx + ly + q*8) * C_TOT + nx + lx];
        __syncthreads();
        #pragma unroll
        for (int q = 0; q < 4; q++)
            g_WTh[(nx + ly + q*8) * IN_F + kx + lx] = __float2half_rn(t[lx][ly + q*8]);
    }
}

// ---------------- kernel 1: h = x@W, fp16 HMMA (K=64/iter) + fused epilogue --
__global__ __launch_bounds__(512) void gemm_xw_mma(const float* __restrict__ avec) {
    __shared__ uint32_t sA[128 * 36];     // 128 rows x 72 halves; reused as sT
    __shared__ uint32_t sB[64 * 36];      // 64 rows x 72 halves; reused as s_part
    __shared__ float s_a[128];

    int tid = threadIdx.x, wid = tid >> 5, lane = tid & 31;
    int gid = lane >> 2, tig = lane & 3;
    int mg = wid & 7, nh = wid >> 3;
    int wrow = mg * 16, ncol0 = nh * 32;
    int n0 = blockIdx.x * 64, m0 = blockIdx.y * 128;
    int head = blockIdx.x;

    if (tid < 128) s_a[tid] = avec[tid];

    float acc[4][4];
    #pragma unroll
    for (int nb = 0; nb < 4; nb++)
        #pragma unroll
        for (int q = 0; q < 4; q++) acc[nb][q] = 0.f;

    int ar = tid >> 2, aq = tid & 3;
    int bn = tid >> 3, bq = tid & 7;
    const __half* aptr = &g_xh [(m0 + ar) * IN_F + aq * 16];
    const __half* bptr = &g_WTh[(n0 + bn) * IN_F + bq * 8];

    uint32_t sa_base = smem_u32(sA);
    uint32_t sb_base = smem_u32(sB);
    int lmrow = (lane & 15) * 72 + (lane >> 4) * 8;

    uint4 av0 = *(const uint4*)(aptr);
    uint4 av1 = *(const uint4*)(aptr + 8);
    uint4 bv  = *(const uint4*)(bptr);

    for (int it = 0; it < 8; it++) {
        __syncthreads();
        *(uint4*)&sA[ar * 36 + aq * 8]     = av0;
        *(uint4*)&sA[ar * 36 + aq * 8 + 4] = av1;
        *(uint4*)&sB[bn * 36 + bq * 4]     = bv;
        if (it < 7) {
            int kk = (it + 1) * 64;
            av0 = *(const uint4*)(aptr + kk);
            av1 = *(const uint4*)(aptr + kk + 8);
            bv  = *(const uint4*)(bptr + kk);
        }
        __syncthreads();

        #pragma unroll
        for (int kst = 0; kst < 4; kst++) {
            int kb = kst * 16;
            uint32_t a[4];
            ldmat_x4(a, sa_base + 2u * (uint32_t)(wrow * 72 + kb + lmrow));
            uint32_t br[2][4];
            #pragma unroll
            for (int nbp = 0; nbp < 2; nbp++)
                ldmat_x4(br[nbp],
                         sb_base + 2u * (uint32_t)((ncol0 + nbp * 16) * 72 + kb + lmrow));
            #pragma unroll
            for (int nb = 0; nb < 4; nb++) {
                int nbp = nb >> 1, hi = nb & 1;
                mma_f16_16n8k16(acc[nb], a, br[nbp][hi], br[nbp][2 + hi]);
            }
        }
    }

    // ---- partial s,t dots over this warp's 32 cols ----
    float sp0 = 0.f, sp1 = 0.f, tp0 = 0.f, tp1 = 0.f;
    #pragma unroll
    for (int nb = 0; nb < 4; nb++) {
        int cb = ncol0 + nb * 8 + 2 * tig;
        float a0 = s_a[cb],      a1 = s_a[cb + 1];
        float d0 = s_a[64 + cb], d1 = s_a[64 + cb + 1];
        sp0 += acc[nb][0] * a0 + acc[nb][1] * a1;
        sp1 += acc[nb][2] * a0 + acc[nb][3] * a1;
        tp0 += acc[nb][0] * d0 + acc[nb][1] * d1;
        tp1 += acc[nb][2] * d0 + acc[nb][3] * d1;
    }
    #pragma unroll
    for (int o = 1; o < 4; o <<= 1) {
        sp0 += __shfl_xor_sync(0xffffffffu, sp0, o);
        sp1 += __shfl_xor_sync(0xffffffffu, sp1, o);
        tp0 += __shfl_xor_sync(0xffffffffu, tp0, o);
        tp1 += __shfl_xor_sync(0xffffffffu, tp1, o);
    }

    __syncthreads();
    float* s_part = (float*)sB;
    if (nh == 1 && tig == 0) {
        s_part[(wrow + gid) * 2]         = sp0;
        s_part[(wrow + gid) * 2 + 1]     = tp0;
        s_part[(wrow + gid + 8) * 2]     = sp1;
        s_part[(wrow + gid + 8) * 2 + 1] = tp1;
    }
    __half* sT = (__half*)sA;
    {
        int rlo = wrow + gid, rhi = rlo + 8;
        #pragma unroll
        for (int nb = 0; nb < 4; nb++) {
            int cb = ncol0 + nb * 8 + 2 * tig;
            sT[cb * 136 + rlo]       = __float2half_rn(acc[nb][0]);
            sT[(cb + 1) * 136 + rlo] = __float2half_rn(acc[nb][1]);
            sT[cb * 136 + rhi]       = __float2half_rn(acc[nb][2]);
            sT[(cb + 1) * 136 + rhi] = __float2half_rn(acc[nb][3]);
        }
    }
    __syncthreads();

    if (nh == 0 && tig == 0) {
        int r0 = wrow + gid, r1 = r0 + 8;
        float s0 = sp0 + s_part[r0 * 2], t0 = tp0 + s_part[r0 * 2 + 1];
        float s1 = sp1 + s_part[r1 * 2], t1 = tp1 + s_part[r1 * 2 + 1];
        int olo = head * N_NODES + m0 + r0, ohi = head * N_NODES + m0 + r1;
        g_esh[olo] = __floats2half2_rn(expf(s0 - ESHIFT), expf(ALPHA * s0 - ESHIFT));
        g_esh[ohi] = __floats2half2_rn(expf(s1 - ESHIFT), expf(ALPHA * s1 - ESHIFT));
        g_ee [olo] = __floats2half2_rn(expf(t0 - ESHIFT), expf(ALPHA * t0 - ESHIFT));
        g_ee [ohi] = __floats2half2_rn(expf(t1 - ESHIFT), expf(ALPHA * t1 - ESHIFT));
    }
    #pragma unroll
    for (int itr = 0; itr < 2; itr++) {
        int idx = itr * 512 + tid;
        int f = idx >> 4, seg = idx & 15;
        uint4 v = *(const uint4*)&sT[f * 136 + seg * 8];
        *(uint4*)&g_hT[(n0 + f) * N_NODES + m0 + seg * 8] = v;
    }
}

// ---------------- kernel 2: aggregation v6 (unchanged, proven) ---------------
#define AGO_EE   0u
#define AGO_B    16384u
#define AGO_RED  51200u
#define AGO_LI   52224u
#define SMEM_AGG 52736
#define B_STRIDE 17408u
#define ONESB    0x3C003C00u

__global__ __launch_bounds__(512, 1) void aggregate_v6(float* __restrict__ out) {
    extern __shared__ char smem[];
    const uint2* st_eeP = (const uint2*)(smem + AGO_EE);
    float* sred  = (float*)(smem + AGO_RED);
    float* slinv = (float*)(smem + AGO_LI);
    float* sAcc  = (float*)(smem + AGO_B);

    int tid = threadIdx.x, wid = tid >> 5, lane = tid & 31;
    int gid = lane >> 2, tig = lane & 3;
    int h = blockIdx.x & 3, i0 = (blockIdx.x >> 2) * 128;
    int mg = wid & 7, ks = wid >> 3;
    int wrow = mg * 16, r0 = wrow + gid, r1 = r0 + 8;

    {
        const uint4* src = (const uint4*)&g_ee[h * N_NODES];
        uint4* dst = (uint4*)(smem + AGO_EE);
        #pragma unroll
        for (int q = 0; q < 2; q++) {
            uint4 v = src[tid + q * 512];
            uint4 o;
            o.x = __byte_perm(v.x, v.y, 0x5410);
            o.y = __byte_perm(v.x, v.y, 0x7632);
            o.z = __byte_perm(v.z, v.w, 0x5410);
            o.w = __byte_perm(v.z, v.w, 0x7632);
            dst[tid + q * 512] = o;
        }
    }
    uint32_t esh0 = *(const uint32_t*)&g_esh[h * N_NODES + i0 + r0];
    uint32_t esh1 = *(const uint32_t*)&g_esh[h * N_NODES + i0 + r1];
    uint32_t eshE0 = __byte_perm(esh0, esh0, 0x1010);
    uint32_t eshA0 = __byte_perm(esh0, esh0, 0x3232);
    uint32_t eshE1 = __byte_perm(esh1, esh1, 0x1010);
    uint32_t eshA1 = __byte_perm(esh1, esh1, 0x3232);
    const uint32_t* mr0 = &g_adjbits[(i0 + r0) * 128 + 2 * ks];
    const uint32_t* mr1 = &g_adjbits[(i0 + r1) * 128 + 2 * ks];

    float acc[8][4], accl[4];
    #pragma unroll
    for (int nb = 0; nb < 8; nb++)
        #pragma unroll
        for (int e = 0; e < 4; e++) acc[nb][e] = 0.f;
    #pragma unroll
    for (int e = 0; e < 4; e++) accl[e] = 0.f;

    int brow = tid >> 3, bcol = (tid & 7) * 16;
    const __half* hTrow = &g_hT[(h * 64 + brow) * N_NODES];
    uint32_t sb_base = smem_u32(smem + AGO_B);
    int lmrow = (lane & 15) * 136 + (lane >> 4) * 8;

    uint2 mw0 = *(const uint2*)mr0;
    uint2 mw1 = *(const uint2*)mr1;
    {
        uint4 pv0 = *(const uint4*)(hTrow + bcol);
        uint4 pv1 = *(const uint4*)(hTrow + bcol + 8);
        __half* B0 = (__half*)(smem + AGO_B);
        *(uint4*)&B0[brow * 136 + bcol]     = pv0;
        *(uint4*)&B0[brow * 136 + bcol + 8] = pv1;
    }
    __syncthreads();

    for (int c = 0; c < 32; c++) {
        int b = c & 1;
        uint4 nv0, nv1; uint2 nm0, nm1;
        if (c < 31) {
            const __half* src = hTrow + (c + 1) * 128;
            nv0 = *(const uint4*)(src + bcol);
            nv1 = *(const uint4*)(src + bcol + 8);
            nm0 = *(const uint2*)(mr0 + 4 * (c + 1));
            nm1 = *(const uint2*)(mr1 + 4 * (c + 1));
        }

        uint32_t afr[4][4];
        int pc = c * 64 + ks * 32;
        #pragma unroll
        for (int kst = 0; kst < 4; kst++) {
            uint32_t w0 = (kst & 2) ? mw0.y : mw0.x;
            uint32_t w1 = (kst & 2) ? mw1.y : mw1.x;
            #pragma unroll
            for (int kp = 0; kp < 2; kp++) {
                int koff = kp * 8 + 2 * tig;
                uint2 ee = st_eeP[pc + kst * 8 + kp * 4 + tig];
                int bit = ((kst & 1) * 16) + koff;
                uint32_t pk = hmax2u(hmul2u(eshE0, ee.x), hmul2u(eshA0, ee.y));
                uint32_t km = (((w0 >> bit) & 1u) ? 0x0000FFFFu : 0u) |
                              (((w0 >> bit) & 2u) ? 0xFFFF0000u : 0u);
                afr[kst][2 * kp] = pk & km;
                pk = hmax2u(hmul2u(eshE1, ee.x), hmul2u(eshA1, ee.y));
                km = (((w1 >> bit) & 1u) ? 0x0000FFFFu : 0u) |
                     (((w1 >> bit) & 2u) ? 0xFFFF0000u : 0u);
                afr[kst][2 * kp + 1] = pk & km;
            }
        }

        {
            uint32_t bufb = sb_base + b * B_STRIDE;
            #pragma unroll
            for (int kst = 0; kst < 4; kst++) {
                int kb = ks * 64 + kst * 16;
                uint32_t br[4][4];
                #pragma unroll
                for (int nbp = 0; nbp < 4; nbp++)
                    ldmat_x4(br[nbp], bufb + 2u * (uint32_t)(nbp * 16 * 136 + kb + lmrow));
                #pragma unroll
                for (int nb = 0; nb < 8; nb++) {
                    int nbp = nb >> 1, hi = nb & 1;
                    mma_f16_16n8k16(acc[nb], afr[kst], br[nbp][hi], br[nbp][2 + hi]);
                }
                mma_f16_16n8k16(accl, afr[kst], ONESB, ONESB);
            }
        }

        if (c < 31) {
            __half* Bd = (__half*)(smem + AGO_B + (b ^ 1) * B_STRIDE);
            *(uint4*)&Bd[brow * 136 + bcol]     = nv0;
            *(uint4*)&Bd[brow * 136 + bcol + 8] = nv1;
            mw0 = nm0; mw1 = nm1;
        }
        __syncthreads();
    }

    if (tig == 0) {
        sred[ks * 128 + r0] = accl[0];
        sred[ks * 128 + r1] = accl[2];
    }
    if (ks == 1) {
        #pragma unroll
        for (int nb = 0; nb < 8; nb++) {
            int cb = nb * 8 + 2 * tig;
            *(float2*)&sAcc[r0 * 66 + cb] = make_float2(acc[nb][0], acc[nb][1]);
            *(float2*)&sAcc[r1 * 66 + cb] = make_float2(acc[nb][2], acc[nb][3]);
        }
    }
    __syncthreads();
    if (tid < 128) slinv[tid] = 1.f / (sred[tid] + sred[128 + tid]);
    __syncthreads();

    if (ks == 0) {
        float inv0 = slinv[r0], inv1 = slinv[r1];
        #pragma unroll
        for (int nb = 0; nb < 8; nb++) {
            int cb = nb * 8 + 2 * tig;
            float2 o0 = *(const float2*)&sAcc[r0 * 66 + cb];
            float2 o1 = *(const float2*)&sAcc[r1 * 66 + cb];
            float2 v0 = make_float2((acc[nb][0] + o0.x) * inv0, (acc[nb][1] + o0.y) * inv0);
            float2 v1 = make_float2((acc[nb][2] + o1.x) * inv1, (acc[nb][3] + o1.y) * inv1);
            *(float2*)&out[(i0 + r0) * C_TOT + h * 64 + cb] = v0;
            *(float2*)&out[(i0 + r1) * C_TOT + h * 64 + cb] = v1;
        }
    }
}

// ---------------- launch: 3-node graph ----------------
extern "C" void kernel_launch(void* const* d_in, const int* in_sizes, int n_in,
                              void* d_out, int out_size) {
    const float* x   = (const float*)d_in[0];
    const int*   adj = (const int*)  d_in[1];
    const float* W   = (const float*)d_in[2];
    const float* a   = (const float*)d_in[3];
    float* out = (float*)d_out;

    static int inited = 0;
    if (!inited) {
        cudaFuncSetAttribute(aggregate_v6,
                             cudaFuncAttributeMaxDynamicSharedMemorySize, SMEM_AGG);
        inited = 1;
    }

    prep<<<PREP_BLOCKS, 256>>>(x, adj, W);
    gemm_xw_mma<<<dim3(C_TOT / 64, N_NODES / 128), 512>>>(a);
    aggregate_v6<<<(N_NODES / 128) * NHEADS, 512, SMEM_AGG>>>(out);
}

// round 16
// speedup vs baseline: 1.4728x; 1.4728x over previous
#include <cuda_runtime.h>
#include <cuda_fp16.h>
#include <cstdint>

#define N_NODES 4096
#define IN_F    512
#define NHEADS  4
#define OUT_F   64
#define C_TOT   256
#define ALPHA   0.2f
#define ESHIFT  2.0f

// ---------------- scratch ----------------
__device__ __half   g_hT  [C_TOT * N_NODES];      // [(h*64+f)][j]  fp16
__device__ __half   g_xh  [N_NODES * IN_F];       // x in fp16
__device__ __half   g_WTh [C_TOT * IN_F];         // W^T in fp16 [n][k]
__device__ __half2  g_esh [NHEADS * N_NODES];     // (exp(s-2), exp(a*s-2))  i-side
__device__ __half2  g_ee  [NHEADS * N_NODES];     // (exp(t-2), exp(a*t-2))  j-side
__device__ uint32_t g_adjbits[N_NODES * (N_NODES / 32)];

// ---------------- helpers ----------------
__device__ __forceinline__ uint32_t smem_u32(const void* p) {
    uint32_t a;
    asm("{ .reg .u64 t; cvta.to.shared.u64 t, %1; cvt.u32.u64 %0, t; }"
        : "=r"(a) : "l"(p));
    return a;
}
__device__ __forceinline__ uint32_t hmul2u(uint32_t a, uint32_t b) {
    uint32_t r; asm("mul.f16x2 %0, %1, %2;" : "=r"(r) : "r"(a), "r"(b)); return r;
}
__device__ __forceinline__ uint32_t hmax2u(uint32_t a, uint32_t b) {
    uint32_t r; asm("max.f16x2 %0, %1, %2;" : "=r"(r) : "r"(a), "r"(b)); return r;
}
__device__ __forceinline__ void mma_f16_16n8k16(float* d, const uint32_t* a,
                                                uint32_t b0, uint32_t b1) {
    asm volatile(
        "mma.sync.aligned.m16n8k16.row.col.f32.f16.f16.f32 "
        "{%0,%1,%2,%3}, {%4,%5,%6,%7}, {%8,%9}, {%0,%1,%2,%3};"
        : "+f"(d[0]), "+f"(d[1]), "+f"(d[2]), "+f"(d[3])
        : "r"(a[0]), "r"(a[1]), "r"(a[2]), "r"(a[3]), "r"(b0), "r"(b1));
}
__device__ __forceinline__ void ldmat_x4(uint32_t* r, uint32_t addr) {
    asm volatile("ldmatrix.sync.aligned.m8n8.x4.shared.b16 {%0,%1,%2,%3}, [%4];"
        : "=r"(r[0]), "=r"(r[1]), "=r"(r[2]), "=r"(r[3]) : "r"(addr));
}

// ---------------- kernel P1: pack adj (MLP=8, warp->8 words) ----------------
__global__ __launch_bounds__(256) void prep_pack(const int* __restrict__ adj) {
    int gw = blockIdx.x * 8 + (threadIdx.x >> 5);
    int lane = threadIdx.x & 31;
    const int* base = adj + gw * 256;
    int v[8];
    #pragma unroll
    for (int i = 0; i < 8; i++) v[i] = base[i * 32 + lane];
    uint32_t w[8];
    #pragma unroll
    for (int i = 0; i < 8; i++) w[i] = __ballot_sync(0xffffffffu, v[i] > 0);
    if (lane == 0) {
        *(uint4*)&g_adjbits[gw * 8]     = make_uint4(w[0], w[1], w[2], w[3]);
        *(uint4*)&g_adjbits[gw * 8 + 4] = make_uint4(w[4], w[5], w[6], w[7]);
    }
}

// ---------------- kernel P2: conv_x | transpose_w ----------------
#define PXW_CONV 2048
__global__ __launch_bounds__(256) void prep_xw(const float* __restrict__ x,
                                               const float* __restrict__ W) {
    __shared__ float t[32][33];
    int b = blockIdx.x;
    if (b < PXW_CONV) {
        int idx = b * 256 + threadIdx.x;
        float4 v = ((const float4*)x)[idx];
        __half2 lo = __floats2half2_rn(v.x, v.y);
        __half2 hi = __floats2half2_rn(v.z, v.w);
        uint2 o = { *(uint32_t*)&lo, *(uint32_t*)&hi };
        ((uint2*)g_xh)[idx] = o;
    } else {
        int bb = b - PXW_CONV;                         // 0..127
        int kx = (bb & 15) * 32, nx = (bb >> 4) * 32;
        int lx = threadIdx.x & 31, ly = threadIdx.x >> 5;
        #pragma unroll
        for (int q = 0; q < 4; q++)
            t[ly + q*8][lx] = W[(kx + ly + q*8) * C_TOT + nx + lx];
        __syncthreads();
        #pragma unroll
        for (int q = 0; q < 4; q++)
            g_WTh[(nx + ly + q*8) * IN_F + kx + lx] = __float2half_rn(t[lx][ly + q*8]);
    }
}

// ---------------- kernel 1: h = x@W, fp16 HMMA (K=64/iter) + fused epilogue --
__global__ __launch_bounds__(512) void gemm_xw_mma(const float* __restrict__ avec) {
    __shared__ uint32_t sA[128 * 36];     // 128 rows x 72 halves; reused as sT
    __shared__ uint32_t sB[64 * 36];      // 64 rows x 72 halves; reused as s_part
    __shared__ float s_a[128];

    int tid = threadIdx.x, wid = tid >> 5, lane = tid & 31;
    int gid = lane >> 2, tig = lane & 3;
    int mg = wid & 7, nh = wid >> 3;
    int wrow = mg * 16, ncol0 = nh * 32;
    int n0 = blockIdx.x * 64, m0 = blockIdx.y * 128;
    int head = blockIdx.x;

    if (tid < 128) s_a[tid] = avec[tid];

    float acc[4][4];
    #pragma unroll
    for (int nb = 0; nb < 4; nb++)
        #pragma unroll
        for (int q = 0; q < 4; q++) acc[nb][q] = 0.f;

    int ar = tid >> 2, aq = tid & 3;
    int bn = tid >> 3, bq = tid & 7;
    const __half* aptr = &g_xh [(m0 + ar) * IN_F + aq * 16];
    const __half* bptr = &g_WTh[(n0 + bn) * IN_F + bq * 8];

    uint32_t sa_base = smem_u32(sA);
    uint32_t sb_base = smem_u32(sB);
    int lmrow = (lane & 15) * 72 + (lane >> 4) * 8;

    uint4 av0 = *(const uint4*)(aptr);
    uint4 av1 = *(const uint4*)(aptr + 8);
    uint4 bv  = *(const uint4*)(bptr);

    for (int it = 0; it < 8; it++) {
        __syncthreads();
        *(uint4*)&sA[ar * 36 + aq * 8]     = av0;
        *(uint4*)&sA[ar * 36 + aq * 8 + 4] = av1;
        *(uint4*)&sB[bn * 36 + bq * 4]     = bv;
        if (it < 7) {
            int kk = (it + 1) * 64;
            av0 = *(const uint4*)(aptr + kk);
            av1 = *(const uint4*)(aptr + kk + 8);
            bv  = *(const uint4*)(bptr + kk);
        }
        __syncthreads();

        #pragma unroll
        for (int kst = 0; kst < 4; kst++) {
            int kb = kst * 16;
            uint32_t a[4];
            ldmat_x4(a, sa_base + 2u * (uint32_t)(wrow * 72 + kb + lmrow));
            uint32_t br[2][4];
            #pragma unroll
            for (int nbp = 0; nbp < 2; nbp++)
                ldmat_x4(br[nbp],
                         sb_base + 2u * (uint32_t)((ncol0 + nbp * 16) * 72 + kb + lmrow));
            #pragma unroll
            for (int nb = 0; nb < 4; nb++) {
                int nbp = nb >> 1, hi = nb & 1;
                mma_f16_16n8k16(acc[nb], a, br[nbp][hi], br[nbp][2 + hi]);
            }
        }
    }

    // ---- partial s,t dots over this warp's 32 cols ----
    float sp0 = 0.f, sp1 = 0.f, tp0 = 0.f, tp1 = 0.f;
    #pragma unroll
    for (int nb = 0; nb < 4; nb++) {
        int cb = ncol0 + nb * 8 + 2 * tig;
        float a0 = s_a[cb],      a1 = s_a[cb + 1];
        float d0 = s_a[64 + cb], d1 = s_a[64 + cb + 1];
        sp0 += acc[nb][0] * a0 + acc[nb][1] * a1;
        sp1 += acc[nb][2] * a0 + acc[nb][3] * a1;
        tp0 += acc[nb][0] * d0 + acc[nb][1] * d1;
        tp1 += acc[nb][2] * d0 + acc[nb][3] * d1;
    }
    #pragma unroll
    for (int o = 1; o < 4; o <<= 1) {
        sp0 += __shfl_xor_sync(0xffffffffu, sp0, o);
        sp1 += __shfl_xor_sync(0xffffffffu, sp1, o);
        tp0 += __shfl_xor_sync(0xffffffffu, tp0, o);
        tp1 += __shfl_xor_sync(0xffffffffu, tp1, o);
    }

    __syncthreads();
    float* s_part = (float*)sB;
    if (nh == 1 && tig == 0) {
        s_part[(wrow + gid) * 2]         = sp0;
        s_part[(wrow + gid) * 2 + 1]     = tp0;
        s_part[(wrow + gid + 8) * 2]     = sp1;
        s_part[(wrow + gid + 8) * 2 + 1] = tp1;
    }
    __half* sT = (__half*)sA;
    {
        int rlo = wrow + gid, rhi = rlo + 8;
        #pragma unroll
        for (int nb = 0; nb < 4; nb++) {
            int cb = ncol0 + nb * 8 + 2 * tig;
            sT[cb * 136 + rlo]       = __float2half_rn(acc[nb][0]);
            sT[(cb + 1) * 136 + rlo] = __float2half_rn(acc[nb][1]);
            sT[cb * 136 + rhi]       = __float2half_rn(acc[nb][2]);
            sT[(cb + 1) * 136 + rhi] = __float2half_rn(acc[nb][3]);
        }
    }
    __syncthreads();

    if (nh == 0 && tig == 0) {
        int r0 = wrow + gid, r1 = r0 + 8;
        float s0 = sp0 + s_part[r0 * 2], t0 = tp0 + s_part[r0 * 2 + 1];
        float s1 = sp1 + s_part[r1 * 2], t1 = tp1 + s_part[r1 * 2 + 1];
        int olo = head * N_NODES + m0 + r0, ohi = head * N_NODES + m0 + r1;
        g_esh[olo] = __floats2half2_rn(expf(s0 - ESHIFT), expf(ALPHA * s0 - ESHIFT));
        g_esh[ohi] = __floats2half2_rn(expf(s1 - ESHIFT), expf(ALPHA * s1 - ESHIFT));
        g_ee [olo] = __floats2half2_rn(expf(t0 - ESHIFT), expf(ALPHA * t0 - ESHIFT));
        g_ee [ohi] = __floats2half2_rn(expf(t1 - ESHIFT), expf(ALPHA * t1 - ESHIFT));
    }
    #pragma unroll
    for (int itr = 0; itr < 2; itr++) {
        int idx = itr * 512 + tid;
        int f = idx >> 4, seg = idx & 15;
        uint4 v = *(const uint4*)&sT[f * 136 + seg * 8];
        *(uint4*)&g_hT[(n0 + f) * N_NODES + m0 + seg * 8] = v;
    }
}

// ---------------- kernel 2: aggregation v6 (unchanged, proven) ---------------
#define AGO_EE   0u
#define AGO_B    16384u
#define AGO_RED  51200u
#define AGO_LI   52224u
#define SMEM_AGG 52736
#define B_STRIDE 17408u
#define ONESB    0x3C003C00u

__global__ __launch_bounds__(512, 1) void aggregate_v6(float* __restrict__ out) {
    extern __shared__ char smem[];
    const uint2* st_eeP = (const uint2*)(smem + AGO_EE);
    float* sred  = (float*)(smem + AGO_RED);
    float* slinv = (float*)(smem + AGO_LI);
    float* sAcc  = (float*)(smem + AGO_B);

    int tid = threadIdx.x, wid = tid >> 5, lane = tid & 31;
    int gid = lane >> 2, tig = lane & 3;
    int h = blockIdx.x & 3, i0 = (blockIdx.x >> 2) * 128;
    int mg = wid & 7, ks = wid >> 3;
    int wrow = mg * 16, r0 = wrow + gid, r1 = r0 + 8;

    {
        const uint4* src = (const uint4*)&g_ee[h * N_NODES];
        uint4* dst = (uint4*)(smem + AGO_EE);
        #pragma unroll
        for (int q = 0; q < 2; q++) {
            uint4 v = src[tid + q * 512];
            uint4 o;
            o.x = __byte_perm(v.x, v.y, 0x5410);
            o.y = __byte_perm(v.x, v.y, 0x7632);
            o.z = __byte_perm(v.z, v.w, 0x5410);
            o.w = __byte_perm(v.z, v.w, 0x7632);
            dst[tid + q * 512] = o;
        }
    }
    uint32_t esh0 = *(const uint32_t*)&g_esh[h * N_NODES + i0 + r0];
    uint32_t esh1 = *(const uint32_t*)&g_esh[h * N_NODES + i0 + r1];
    uint32_t eshE0 = __byte_perm(esh0, esh0, 0x1010);
    uint32_t eshA0 = __byte_perm(esh0, esh0, 0x3232);
    uint32_t eshE1 = __byte_perm(esh1, esh1, 0x1010);
    uint32_t eshA1 = __byte_perm(esh1, esh1, 0x3232);
    const uint32_t* mr0 = &g_adjbits[(i0 + r0) * 128 + 2 * ks];
    const uint32_t* mr1 = &g_adjbits[(i0 + r1) * 128 + 2 * ks];

    float acc[8][4], accl[4];
    #pragma unroll
    for (int nb = 0; nb < 8; nb++)
        #pragma unroll
        for (int e = 0; e < 4; e++) acc[nb][e] = 0.f;
    #pragma unroll
    for (int e = 0; e < 4; e++) accl[e] = 0.f;

    int brow = tid >> 3, bcol = (tid & 7) * 16;
    const __half* hTrow = &g_hT[(h * 64 + brow) * N_NODES];
    uint32_t sb_base = smem_u32(smem + AGO_B);
    int lmrow = (lane & 15) * 136 + (lane >> 4) * 8;

    uint2 mw0 = *(const uint2*)mr0;
    uint2 mw1 = *(const uint2*)mr1;
    {
        uint4 pv0 = *(const uint4*)(hTrow + bcol);
        uint4 pv1 = *(const uint4*)(hTrow + bcol + 8);
        __half* B0 = (__half*)(smem + AGO_B);
        *(uint4*)&B0[brow * 136 + bcol]     = pv0;
        *(uint4*)&B0[brow * 136 + bcol + 8] = pv1;
    }
    __syncthreads();

    for (int c = 0; c < 32; c++) {
        int b = c & 1;
        uint4 nv0, nv1; uint2 nm0, nm1;
        if (c < 31) {
            const __half* src = hTrow + (c + 1) * 128;
            nv0 = *(const uint4*)(src + bcol);
            nv1 = *(const uint4*)(src + bcol + 8);
            nm0 = *(const uint2*)(mr0 + 4 * (c + 1));
            nm1 = *(const uint2*)(mr1 + 4 * (c + 1));
        }

        uint32_t afr[4][4];
        int pc = c * 64 + ks * 32;
        #pragma unroll
        for (int kst = 0; kst < 4; kst++) {
            uint32_t w0 = (kst & 2) ? mw0.y : mw0.x;
            uint32_t w1 = (kst & 2) ? mw1.y : mw1.x;
            #pragma unroll
            for (int kp = 0; kp < 2; kp++) {
                int koff = kp * 8 + 2 * tig;
                uint2 ee = st_eeP[pc + kst * 8 + kp * 4 + tig];
                int bit = ((kst & 1) * 16) + koff;
                uint32_t pk = hmax2u(hmul2u(eshE0, ee.x), hmul2u(eshA0, ee.y));
                uint32_t km = (((w0 >> bit) & 1u) ? 0x0000FFFFu : 0u) |
                              (((w0 >> bit) & 2u) ? 0xFFFF0000u : 0u);
                afr[kst][2 * kp] = pk & km;
                pk = hmax2u(hmul2u(eshE1, ee.x), hmul2u(eshA1, ee.y));
                km = (((w1 >> bit) & 1u) ? 0x0000FFFFu : 0u) |
                     (((w1 >> bit) & 2u) ? 0xFFFF0000u : 0u);
                afr[kst][2 * kp + 1] = pk & km;
            }
        }

        {
            uint32_t bufb = sb_base + b * B_STRIDE;
            #pragma unroll
            for (int kst = 0; kst < 4; kst++) {
                int kb = ks * 64 + kst * 16;
                uint32_t br[4][4];
                #pragma unroll
                for (int nbp = 0; nbp < 4; nbp++)
                    ldmat_x4(br[nbp], bufb + 2u * (uint32_t)(nbp * 16 * 136 + kb + lmrow));
                #pragma unroll
                for (int nb = 0; nb < 8; nb++) {
                    int nbp = nb >> 1, hi = nb & 1;
                    mma_f16_16n8k16(acc[nb], afr[kst], br[nbp][hi], br[nbp][2 + hi]);
                }
                mma_f16_16n8k16(accl, afr[kst], ONESB, ONESB);
            }
        }

        if (c < 31) {
            __half* Bd = (__half*)(smem + AGO_B + (b ^ 1) * B_STRIDE);
            *(uint4*)&Bd[brow * 136 + bcol]     = nv0;
            *(uint4*)&Bd[brow * 136 + bcol + 8] = nv1;
            mw0 = nm0; mw1 = nm1;
        }
        __syncthreads();
    }

    if (tig == 0) {
        sred[ks * 128 + r0] = accl[0];
        sred[ks * 128 + r1] = accl[2];
    }
    if (ks == 1) {
        #pragma unroll
        for (int nb = 0; nb < 8; nb++) {
            int cb = nb * 8 + 2 * tig;
            *(float2*)&sAcc[r0 * 66 + cb] = make_float2(acc[nb][0], acc[nb][1]);
            *(float2*)&sAcc[r1 * 66 + cb] = make_float2(acc[nb][2], acc[nb][3]);
        }
    }
    __syncthreads();
    if (tid < 128) slinv[tid] = 1.f / (sred[tid] + sred[128 + tid]);
    __syncthreads();

    if (ks == 0) {
        float inv0 = slinv[r0], inv1 = slinv[r1];
        #pragma unroll
        for (int nb = 0; nb < 8; nb++) {
            int cb = nb * 8 + 2 * tig;
            float2 o0 = *(const float2*)&sAcc[r0 * 66 + cb];
            float2 o1 = *(const float2*)&sAcc[r1 * 66 + cb];
            float2 v0 = make_float2((acc[nb][0] + o0.x) * inv0, (acc[nb][1] + o0.y) * inv0);
            float2 v1 = make_float2((acc[nb][2] + o1.x) * inv1, (acc[nb][3] + o1.y) * inv1);
            *(float2*)&out[(i0 + r0) * C_TOT + h * 64 + cb] = v0;
            *(float2*)&out[(i0 + r1) * C_TOT + h * 64 + cb] = v1;
        }
    }
}

// ---------------- launch: pack forked parallel to conv/trans->gemm ----------
extern "C" void kernel_launch(void* const* d_in, const int* in_sizes, int n_in,
                              void* d_out, int out_size) {
    const float* x   = (const float*)d_in[0];
    const int*   adj = (const int*)  d_in[1];
    const float* W   = (const float*)d_in[2];
    const float* a   = (const float*)d_in[3];
    float* out = (float*)d_out;

    static cudaStream_t s2 = nullptr;
    static cudaEvent_t evF = nullptr, evJ = nullptr;
    if (!s2) {
        cudaStreamCreate(&s2);
        cudaEventCreateWithFlags(&evF, cudaEventDisableTiming);
        cudaEventCreateWithFlags(&evJ, cudaEventDisableTiming);
        cudaFuncSetAttribute(aggregate_v6,
                             cudaFuncAttributeMaxDynamicSharedMemorySize, SMEM_AGG);
    }

    cudaEventRecord(evF, 0);
    cudaStreamWaitEvent(s2, evF, 0);
    prep_pack<<<N_NODES * N_NODES / 2048, 256, 0, s2>>>(adj);
    cudaEventRecord(evJ, s2);

    prep_xw<<<PXW_CONV + 128, 256>>>(x, W);
    gemm_xw_mma<<<dim3(C_TOT / 64, N_NODES / 128), 512>>>(a);

    cudaStreamWaitEvent(0, evJ, 0);
    aggregate_v6<<<(N_NODES / 128) * NHEADS, 512, SMEM_AGG>>>(out);
}